// round 9
// baseline (speedup 1.0000x reference)
#include <cuda_runtime.h>
#include <cuda_bf16.h>
#include <cstdint>

// out[n, d] = input[n, d] * W[d];  N=16384, D=4096, fp32.
// Pure stream: 256MB read + 256MB write. DRAM-bound; measured sustained
// ceiling ~6.25TB/s (bench pinned ~82us across 6 structural variants).
//
// R7: single-wave persistent layout. GRID=512 CTAs (1 wave on 148 SMs),
// each owning a contiguous 512KB span, iterating 16 batches of 4
// front-batched 256-bit loads/stores (.cs streaming). Eliminates wave
// transitions and amortizes the drain tail. W stays in registers.

static constexpr int N_ROWS  = 16384;
static constexpr int D8      = 4096 / 8;           // 512 v8-chunks per row
static constexpr int THREADS = 256;
static constexpr int R       = 4;                  // v8 accesses per batch
static constexpr int BATCHES = 16;                 // batches per CTA
static constexpr long long TOTAL8 = (long long)N_ROWS * D8;  // 2^23
static constexpr int GRID = (int)(TOTAL8 / ((long long)THREADS * R * BATCHES)); // 512
static constexpr int CTA_SPAN = THREADS * R * BATCHES;       // 16384 chunks

__global__ void __launch_bounds__(THREADS) diag_scale_persist_kernel(
    const float* __restrict__ in,
    const float* __restrict__ w,
    float* __restrict__ out)
{
    // CTA owns chunks [b*16384, (b+1)*16384) — contiguous 512KB.
    // 16384 % 512 == 0, so within every batch, iteration i has
    // column = tid + (i&1)*256 (chunk index ≡ tid + i*256 mod 512).
    unsigned base0 = blockIdx.x * (unsigned)CTA_SPAN + threadIdx.x;

    const float4* w4 = (const float4*)w;
    float4 we0 = __ldg(&w4[threadIdx.x * 2]);
    float4 we1 = __ldg(&w4[threadIdx.x * 2 + 1]);
    float4 wo0 = __ldg(&w4[(threadIdx.x + 256) * 2]);
    float4 wo1 = __ldg(&w4[(threadIdx.x + 256) * 2 + 1]);

    for (int b = 0; b < BATCHES; b++) {
        unsigned base = base0 + (unsigned)b * (THREADS * R);

        float a[R][8];
#pragma unroll
        for (int i = 0; i < R; i++) {
            const float* p = in + (size_t)(base + i * THREADS) * 8;
            asm volatile(
                "ld.global.cs.v8.f32 {%0,%1,%2,%3,%4,%5,%6,%7}, [%8];"
                : "=f"(a[i][0]), "=f"(a[i][1]), "=f"(a[i][2]), "=f"(a[i][3]),
                  "=f"(a[i][4]), "=f"(a[i][5]), "=f"(a[i][6]), "=f"(a[i][7])
                : "l"(p));
        }

#pragma unroll
        for (int i = 0; i < R; i++) {
            float4 wl = (i & 1) ? wo0 : we0;
            float4 wh = (i & 1) ? wo1 : we1;
            float r0 = a[i][0] * wl.x, r1 = a[i][1] * wl.y;
            float r2 = a[i][2] * wl.z, r3 = a[i][3] * wl.w;
            float r4 = a[i][4] * wh.x, r5 = a[i][5] * wh.y;
            float r6 = a[i][6] * wh.z, r7 = a[i][7] * wh.w;
            float* p = out + (size_t)(base + i * THREADS) * 8;
            asm volatile(
                "st.global.cs.v8.f32 [%0], {%1,%2,%3,%4,%5,%6,%7,%8};"
                :: "l"(p),
                   "f"(r0), "f"(r1), "f"(r2), "f"(r3),
                   "f"(r4), "f"(r5), "f"(r6), "f"(r7)
                : "memory");
        }
    }
}

extern "C" void kernel_launch(void* const* d_in, const int* in_sizes, int n_in,
                              void* d_out, int out_size) {
    const float* in = (const float*)d_in[0];
    const float* w  = (const float*)d_in[1];
    float* out = (float*)d_out;
    diag_scale_persist_kernel<<<GRID, THREADS>>>(in, w, out);
}

// round 10
// speedup vs baseline: 1.1799x; 1.1799x over previous
#include <cuda_runtime.h>
#include <cuda_bf16.h>
#include <cstdint>

// out[n, d] = input[n, d] * W[d];  N=16384, D=4096, fp32.
// Pure stream: 256MB read + 256MB write. DRAM-bound.
//
// FINAL (revert of R7 persistent experiment, which regressed to 96.8us by
// collapsing chipwide request concurrency): oversubscribed grid keeps the
// memory queues full across wave transitions.
//
// Config = session best (81.95us bench, ~6.5TB/s ncu-window):
//  - 256-bit accesses (LDG.E.256 / STG.E.256) via ld/st.global.cs.v8.f32
//  - .cs streaming policy on both streams (no-reuse data)
//  - R=4 chunks/thread, grid=8192 (many resident CTAs, ~58 regs)
//  - CTA owns a contiguous 32KB span; W held in 4 registers/thread
// Measured floor: 512MB / ~82us = ~6.25TB/s sustained under graph replay.

static constexpr int N_ROWS  = 16384;
static constexpr int D8      = 4096 / 8;            // 512 v8-chunks per row
static constexpr int THREADS = 256;
static constexpr int R       = 4;                   // v8 accesses per thread
static constexpr long long TOTAL8 = (long long)N_ROWS * D8;     // 8,388,608
static constexpr int GRID    = (int)(TOTAL8 / (THREADS * R));   // 8192

__global__ void __launch_bounds__(THREADS) diag_scale_final_kernel(
    const float* __restrict__ in,
    const float* __restrict__ w,
    float* __restrict__ out)
{
    // Chunk index = base + i*256. base % 512 == tid, so the D-column of
    // iteration i is tid + (i&1)*256: only two W vectors needed per thread.
    unsigned base = blockIdx.x * (THREADS * R) + threadIdx.x;

    const float4* w4 = (const float4*)w;
    float4 we0 = __ldg(&w4[threadIdx.x * 2]);
    float4 we1 = __ldg(&w4[threadIdx.x * 2 + 1]);
    float4 wo0 = __ldg(&w4[(threadIdx.x + 256) * 2]);
    float4 wo1 = __ldg(&w4[(threadIdx.x + 256) * 2 + 1]);

    float a[R][8];
#pragma unroll
    for (int i = 0; i < R; i++) {
        const float* p = in + (size_t)(base + i * THREADS) * 8;
        asm volatile(
            "ld.global.cs.v8.f32 {%0,%1,%2,%3,%4,%5,%6,%7}, [%8];"
            : "=f"(a[i][0]), "=f"(a[i][1]), "=f"(a[i][2]), "=f"(a[i][3]),
              "=f"(a[i][4]), "=f"(a[i][5]), "=f"(a[i][6]), "=f"(a[i][7])
            : "l"(p));
    }

#pragma unroll
    for (int i = 0; i < R; i++) {
        float4 wl = (i & 1) ? wo0 : we0;
        float4 wh = (i & 1) ? wo1 : we1;
        float r0 = a[i][0] * wl.x, r1 = a[i][1] * wl.y;
        float r2 = a[i][2] * wl.z, r3 = a[i][3] * wl.w;
        float r4 = a[i][4] * wh.x, r5 = a[i][5] * wh.y;
        float r6 = a[i][6] * wh.z, r7 = a[i][7] * wh.w;
        float* p = out + (size_t)(base + i * THREADS) * 8;
        asm volatile(
            "st.global.cs.v8.f32 [%0], {%1,%2,%3,%4,%5,%6,%7,%8};"
            :: "l"(p),
               "f"(r0), "f"(r1), "f"(r2), "f"(r3),
               "f"(r4), "f"(r5), "f"(r6), "f"(r7)
            : "memory");
    }
}

extern "C" void kernel_launch(void* const* d_in, const int* in_sizes, int n_in,
                              void* d_out, int out_size) {
    const float* in = (const float*)d_in[0];
    const float* w  = (const float*)d_in[1];
    float* out = (float*)d_out;
    diag_scale_final_kernel<<<GRID, THREADS>>>(in, w, out);
}

// round 11
// speedup vs baseline: 1.1803x; 1.0004x over previous
#include <cuda_runtime.h>
#include <cuda_bf16.h>
#include <cstdint>

// out[n, d] = input[n, d] * W[d];  N=16384, D=4096, fp32.
// Pure stream: 256MB read + 256MB write. DRAM-bound at the measured
// sustained ceiling of ~6.25TB/s (bench floor 82.0±0.4us over 8 variants).
//
// R9: max standing concurrency. grid=16384, R=2 v8-chunks/thread (~40 regs,
// higher occupancy, biggest ready-CTA pool to fill memory queues during
// wave transitions / drain tail). Keeps everything proven optimal:
// 256-bit .cs loads/stores, contiguous 16KB span per CTA, W in registers.

static constexpr int N_ROWS  = 16384;
static constexpr int D8      = 4096 / 8;            // 512 v8-chunks per row
static constexpr int THREADS = 256;
static constexpr int R       = 2;                   // v8 accesses per thread
static constexpr long long TOTAL8 = (long long)N_ROWS * D8;     // 8,388,608
static constexpr int GRID    = (int)(TOTAL8 / (THREADS * R));   // 16384

__global__ void __launch_bounds__(THREADS) diag_scale_maxconc_kernel(
    const float* __restrict__ in,
    const float* __restrict__ w,
    float* __restrict__ out)
{
    // Chunk index = base + i*256; base % 512 == tid, so column of iteration
    // i is tid + (i&1)*256. With R=2: i=0 -> col=tid, i=1 -> col=tid+256.
    unsigned base = blockIdx.x * (THREADS * R) + threadIdx.x;

    const float4* w4 = (const float4*)w;
    float4 we0 = __ldg(&w4[threadIdx.x * 2]);
    float4 we1 = __ldg(&w4[threadIdx.x * 2 + 1]);
    float4 wo0 = __ldg(&w4[(threadIdx.x + 256) * 2]);
    float4 wo1 = __ldg(&w4[(threadIdx.x + 256) * 2 + 1]);

    float a[R][8];
#pragma unroll
    for (int i = 0; i < R; i++) {
        const float* p = in + (size_t)(base + i * THREADS) * 8;
        asm volatile(
            "ld.global.cs.v8.f32 {%0,%1,%2,%3,%4,%5,%6,%7}, [%8];"
            : "=f"(a[i][0]), "=f"(a[i][1]), "=f"(a[i][2]), "=f"(a[i][3]),
              "=f"(a[i][4]), "=f"(a[i][5]), "=f"(a[i][6]), "=f"(a[i][7])
            : "l"(p));
    }

#pragma unroll
    for (int i = 0; i < R; i++) {
        float4 wl = (i & 1) ? wo0 : we0;
        float4 wh = (i & 1) ? wo1 : we1;
        float r0 = a[i][0] * wl.x, r1 = a[i][1] * wl.y;
        float r2 = a[i][2] * wl.z, r3 = a[i][3] * wl.w;
        float r4 = a[i][4] * wh.x, r5 = a[i][5] * wh.y;
        float r6 = a[i][6] * wh.z, r7 = a[i][7] * wh.w;
        float* p = out + (size_t)(base + i * THREADS) * 8;
        asm volatile(
            "st.global.cs.v8.f32 [%0], {%1,%2,%3,%4,%5,%6,%7,%8};"
            :: "l"(p),
               "f"(r0), "f"(r1), "f"(r2), "f"(r3),
               "f"(r4), "f"(r5), "f"(r6), "f"(r7)
            : "memory");
    }
}

extern "C" void kernel_launch(void* const* d_in, const int* in_sizes, int n_in,
                              void* d_out, int out_size) {
    const float* in = (const float*)d_in[0];
    const float* w  = (const float*)d_in[1];
    float* out = (float*)d_out;
    diag_scale_maxconc_kernel<<<GRID, THREADS>>>(in, w, out);
}